// round 15
// baseline (speedup 1.0000x reference)
#include <cuda_runtime.h>
#include <cstdint>

// Neural-ODE explicit Euler, 20 fused steps — mma.sync tf32, crossbar-optimized retile.
// B=8192, LATENT=256, U=16, HIDDEN=512. TM=64 rows/CTA, grid=128, 256 thr (8 warps).
//
// Warp grid: wm in {0,1} (32 m-rows), wn in {0..3}.
//   GEMM1 warp tile 32m x 32n (chunk = 128 H-cols, 4 chunks/step): 256 B LDS per MMA
//   GEMM2 warp tile 32m x 64n (full N=256):                        192 B LDS per MMA
// z state lives in REGISTERS (same fragment ownership as d2 accumulator);
// dumped once/step to SMEM as tf32 (k,k+4)-paired layout -> zero cvt in G1 loop.
// All operand loads are LDS.64 pairs; strides chosen ≡ 4 (mod 16) in 8B units
// so every 16-lane phase hits 16 distinct banks.
//
// SMEM (8B units):
//   Ztf [136 pairs][68 rows]   z|u tf32 pairs        73.9 KB
//   W1p [68 pairs][132 n]      half-K slab of W1     71.8 KB
//   Hp  [64 pairs][68 rows]    H chunk (128 cols)    34.8 KB
//   W2p [16 pairs][260 n]      32-row W2 sub-slice   33.3 KB
//   b1s[512] b2s[256] hs[64]                          3.3 KB   => 217,216 B total

#define NSTEPS  20
#define THREADS 256
#define LATENT  256
#define UDIM    16
#define HIDDEN  512

#define ZTF_OFF 0
#define ZTF_SZ  (136*68)
#define W1P_OFF (ZTF_OFF + ZTF_SZ)
#define W1P_SZ  (68*132)
#define HP_OFF  (W1P_OFF + W1P_SZ)
#define HP_SZ   (64*68)
#define W2P_OFF (HP_OFF + HP_SZ)
#define W2P_SZ  (16*260)
#define SMEM8   (W2P_OFF + W2P_SZ)
#define SMEM_BYTES (SMEM8*8 + (512+256+64)*4)

__device__ __forceinline__ uint32_t f2tf(float f) {
    uint32_t u; asm("cvt.rna.tf32.f32 %0, %1;" : "=r"(u) : "f"(f)); return u;
}
__device__ __forceinline__ float tanh_hw(float x) {
    float y; asm("tanh.approx.f32 %0, %1;" : "=f"(y) : "f"(x)); return y;
}
__device__ __forceinline__ void mma8(float* d, uint32_t a0, uint32_t a1,
                                     uint32_t a2, uint32_t a3,
                                     uint32_t b0, uint32_t b1) {
    asm("mma.sync.aligned.m16n8k8.row.col.f32.tf32.tf32.f32 "
        "{%0,%1,%2,%3}, {%4,%5,%6,%7}, {%8,%9}, {%0,%1,%2,%3};"
        : "+f"(d[0]), "+f"(d[1]), "+f"(d[2]), "+f"(d[3])
        : "r"(a0), "r"(a1), "r"(a2), "r"(a3), "r"(b0), "r"(b1));
}

__global__ __launch_bounds__(THREADS, 1)
void node_euler_hmma2(const float* __restrict__ zt,
                      const float* __restrict__ dt,
                      const float* __restrict__ ut,
                      const float* __restrict__ W1,
                      const float* __restrict__ b1,
                      const float* __restrict__ W2,
                      const float* __restrict__ b2,
                      float* __restrict__ out)
{
    extern __shared__ uint2 sm8[];
    uint2* Ztf = sm8 + ZTF_OFF;
    uint2* W1p = sm8 + W1P_OFF;
    uint2* Hp  = sm8 + HP_OFF;
    uint2* W2p = sm8 + W2P_OFF;
    float* b1s = (float*)(sm8 + SMEM8);
    float* b2s = b1s + 512;
    float* hs  = b2s + 256;

    const int tid  = threadIdx.x;
    const int w    = tid >> 5, lane = tid & 31;
    const int g    = lane >> 2, tig = lane & 3;
    const int wm   = w >> 2;          // 0..1
    const int wn   = w & 3;           // 0..3
    const int m0   = wm * 32;
    const int row0 = blockIdx.x * 64;

    // ---- init biases / step sizes / u-pairs (static part of Ztf) ----
    for (int i = tid; i < HIDDEN; i += THREADS) b1s[i] = b1[i];
    b2s[tid] = b2[tid];
    if (tid < 64) hs[tid] = dt[row0 + tid] * (1.0f / NSTEPS);
    for (int i = tid; i < 8 * 64; i += THREADS) {
        int pp = i >> 6, r = i & 63;
        int klo = ((pp >> 2) << 3) + (pp & 3);    // u col of pair lo (hi = +4)
        Ztf[(128 + pp) * 68 + r] =
            make_uint2(f2tf(ut[(row0 + r) * UDIM + klo]),
                       f2tf(ut[(row0 + r) * UDIM + klo + 4]));
    }

    // ---- z state into registers (fragment ownership == d2 layout) ----
    float z[2][8][4];
    #pragma unroll
    for (int mt = 0; mt < 2; mt++)
        #pragma unroll
        for (int nt = 0; nt < 8; nt++) {
            int r = row0 + m0 + mt * 16 + g;
            int c = wn * 64 + nt * 8 + 2 * tig;
            float2 v0 = *(const float2*)(zt + (size_t)r * LATENT + c);
            float2 v1 = *(const float2*)(zt + (size_t)(r + 8) * LATENT + c);
            z[mt][nt][0] = v0.x; z[mt][nt][1] = v0.y;
            z[mt][nt][2] = v1.x; z[mt][nt][3] = v1.y;
        }
    __syncthreads();
    float hr[2][2];
    #pragma unroll
    for (int mt = 0; mt < 2; mt++) {
        hr[mt][0] = hs[m0 + mt * 16 + g];
        hr[mt][1] = hs[m0 + mt * 16 + g + 8];
    }

    float d2[2][8][4];
    #pragma unroll
    for (int mt = 0; mt < 2; mt++)
        #pragma unroll
        for (int nt = 0; nt < 8; nt++)
            d2[mt][nt][0] = d2[mt][nt][1] = d2[mt][nt][2] = d2[mt][nt][3] = 0.0f;

    for (int s = 0; s < NSTEPS; s++) {
        // ---- dump z (tf32) into Ztf pair layout; conflict-free STS.32 ----
        uint32_t* Zf = (uint32_t*)Ztf;
        #pragma unroll
        for (int mt = 0; mt < 2; mt++)
            #pragma unroll
            for (int nt = 0; nt < 8; nt++) {
                int r  = m0 + mt * 16 + g;
                int c  = wn * 64 + nt * 8 + 2 * tig;
                int p0 = ((c >> 3) << 2) + (c & 3),  h0 = (c >> 2) & 1;
                int c1 = c + 1;
                int p1 = ((c1 >> 3) << 2) + (c1 & 3), h1 = (c1 >> 2) & 1;
                Zf[(p0 * 68 + r) * 2 + h0]       = f2tf(z[mt][nt][0]);
                Zf[(p1 * 68 + r) * 2 + h1]       = f2tf(z[mt][nt][1]);
                Zf[(p0 * 68 + r + 8) * 2 + h0]   = f2tf(z[mt][nt][2]);
                Zf[(p1 * 68 + r + 8) * 2 + h1]   = f2tf(z[mt][nt][3]);
            }
        __syncthreads();

        for (int c4 = 0; c4 < 4; c4++) {          // 4 chunks of 128 H-cols
            float d1[2][4][4];
            #pragma unroll
            for (int mt = 0; mt < 2; mt++)
                #pragma unroll
                for (int tn = 0; tn < 4; tn++)
                    d1[mt][tn][0] = d1[mt][tn][1] = d1[mt][tn][2] = d1[mt][tn][3] = 0.0f;

            // ===== GEMM1: K=272 streamed in two 136-k slabs =====
            #pragma unroll 1
            for (int slab = 0; slab < 2; slab++) {
                for (int it = 0; it < 34; it++) {
                    int idx = tid + THREADS * it;
                    int n = idx & 127, pl = idx >> 7;
                    int klo = slab * 136 + ((pl >> 2) << 3) + (pl & 3);
                    W1p[pl * 132 + n] =
                        make_uint2(f2tf(W1[(size_t)klo * HIDDEN + c4 * 128 + n]),
                                   f2tf(W1[(size_t)(klo + 4) * HIDDEN + c4 * 128 + n]));
                }
                __syncthreads();
                #pragma unroll 1
                for (int ktl = 0; ktl < 17; ktl++) {
                    int p = (slab * 17 + ktl) * 4 + tig;
                    uint2 A00 = Ztf[p * 68 + m0 + g];
                    uint2 A01 = Ztf[p * 68 + m0 + g + 8];
                    uint2 A10 = Ztf[p * 68 + m0 + 16 + g];
                    uint2 A11 = Ztf[p * 68 + m0 + 16 + g + 8];
                    int pl = ktl * 4 + tig;
                    #pragma unroll
                    for (int tn = 0; tn < 4; tn++) {
                        uint2 B = W1p[pl * 132 + wn * 32 + tn * 8 + g];
                        mma8(d1[0][tn], A00.x, A01.x, A00.y, A01.y, B.x, B.y);
                        mma8(d1[1][tn], A10.x, A11.x, A10.y, A11.y, B.x, B.y);
                    }
                }
                __syncthreads();
            }

            // ===== bias + tanh -> Hp (tf32 pairs) =====
            uint32_t* Hf = (uint32_t*)Hp;
            #pragma unroll
            for (int mt = 0; mt < 2; mt++)
                #pragma unroll
                for (int tn = 0; tn < 4; tn++) {
                    int lc = wn * 32 + tn * 8 + 2 * tig;
                    int gc = c4 * 128 + lc;
                    float bv0 = b1s[gc], bv1 = b1s[gc + 1];
                    int r  = m0 + mt * 16 + g;
                    int p0 = ((lc >> 3) << 2) + (lc & 3),  h0 = (lc >> 2) & 1;
                    int l1 = lc + 1;
                    int p1 = ((l1 >> 3) << 2) + (l1 & 3),  h1 = (l1 >> 2) & 1;
                    Hf[(p0 * 68 + r) * 2 + h0]     = f2tf(tanh_hw(d1[mt][tn][0] + bv0));
                    Hf[(p1 * 68 + r) * 2 + h1]     = f2tf(tanh_hw(d1[mt][tn][1] + bv1));
                    Hf[(p0 * 68 + r + 8) * 2 + h0] = f2tf(tanh_hw(d1[mt][tn][2] + bv0));
                    Hf[(p1 * 68 + r + 8) * 2 + h1] = f2tf(tanh_hw(d1[mt][tn][3] + bv1));
                }
            __syncthreads();

            // ===== GEMM2: accumulate this chunk's 128 H-cols in 4 k-subs =====
            #pragma unroll 1
            for (int sub = 0; sub < 4; sub++) {
                for (int it = 0; it < 16; it++) {
                    int idx = tid + THREADS * it;
                    int n = idx & 255, pl = idx >> 8;
                    int klo = c4 * 128 + sub * 32 + ((pl >> 2) << 3) + (pl & 3);
                    W2p[pl * 260 + n] =
                        make_uint2(f2tf(W2[(size_t)klo * LATENT + n]),
                                   f2tf(W2[(size_t)(klo + 4) * LATENT + n]));
                }
                __syncthreads();
                #pragma unroll
                for (int kt2 = 0; kt2 < 4; kt2++) {
                    int ph = (sub * 4 + kt2) * 4 + tig;
                    uint2 A00 = Hp[ph * 68 + m0 + g];
                    uint2 A01 = Hp[ph * 68 + m0 + g + 8];
                    uint2 A10 = Hp[ph * 68 + m0 + 16 + g];
                    uint2 A11 = Hp[ph * 68 + m0 + 16 + g + 8];
                    int pl = kt2 * 4 + tig;
                    #pragma unroll
                    for (int nt = 0; nt < 8; nt++) {
                        uint2 B = W2p[pl * 260 + wn * 64 + nt * 8 + g];
                        mma8(d2[0][nt], A00.x, A01.x, A00.y, A01.y, B.x, B.y);
                        mma8(d2[1][nt], A10.x, A11.x, A10.y, A11.y, B.x, B.y);
                    }
                }
                __syncthreads();
            }
        }

        // ---- z += h * (d2 + b2); reset d2 (registers only; no sync needed) ----
        #pragma unroll
        for (int mt = 0; mt < 2; mt++)
            #pragma unroll
            for (int nt = 0; nt < 8; nt++) {
                int c = wn * 64 + nt * 8 + 2 * tig;
                z[mt][nt][0] += hr[mt][0] * (d2[mt][nt][0] + b2s[c]);
                z[mt][nt][1] += hr[mt][0] * (d2[mt][nt][1] + b2s[c + 1]);
                z[mt][nt][2] += hr[mt][1] * (d2[mt][nt][2] + b2s[c]);
                z[mt][nt][3] += hr[mt][1] * (d2[mt][nt][3] + b2s[c + 1]);
                d2[mt][nt][0] = d2[mt][nt][1] = d2[mt][nt][2] = d2[mt][nt][3] = 0.0f;
            }
    }

    // ---- write result from registers ----
    #pragma unroll
    for (int mt = 0; mt < 2; mt++)
        #pragma unroll
        for (int nt = 0; nt < 8; nt++) {
            int r = row0 + m0 + mt * 16 + g;
            int c = wn * 64 + nt * 8 + 2 * tig;
            *(float2*)(out + (size_t)r * LATENT + c)       = make_float2(z[mt][nt][0], z[mt][nt][1]);
            *(float2*)(out + (size_t)(r + 8) * LATENT + c) = make_float2(z[mt][nt][2], z[mt][nt][3]);
        }
}

extern "C" void kernel_launch(void* const* d_in, const int* in_sizes, int n_in,
                              void* d_out, int out_size)
{
    const float* zt = (const float*)d_in[0];
    const float* dt = (const float*)d_in[1];
    const float* ut = (const float*)d_in[2];
    const float* W1 = (const float*)d_in[3];
    const float* b1 = (const float*)d_in[4];
    const float* W2 = (const float*)d_in[5];
    const float* b2 = (const float*)d_in[6];
    float* out = (float*)d_out;

    cudaFuncSetAttribute(node_euler_hmma2,
                         cudaFuncAttributeMaxDynamicSharedMemorySize, SMEM_BYTES);

    node_euler_hmma2<<<128, THREADS, SMEM_BYTES>>>(zt, dt, ut, W1, b1, W2, b2, out);
}

// round 17
// speedup vs baseline: 1.0845x; 1.0845x over previous
#include <cuda_runtime.h>
#include <cstdint>

// Neural-ODE explicit Euler, 20 fused steps — mma.sync tf32, latency-hidden staging.
// B=8192, LATENT=256, U=16, HIDDEN=512. TM=64 rows/CTA, grid=128, 256 thr (8 warps).
//
// R15 changes vs R14 (which proved crossbar was NOT binding; issue=40% was):
//  * weight staging done in fully-unrolled 17/16-pair register batches (MLP~34)
//  * next slab/sub's LDG batch issued BEFORE the barrier+MMA of the current one
//  * z state back in SMEM as fp32 pairs (kills the 255-reg spills); GEMM1 A-path
//    converts to tf32 on load (8 cvt per kt-iter)
//
// SMEM (8B units):
//   Zs  [136 pairs][68 rows]  fp32 (k,k+4) pairs, z cols 0..255 + u 256..271
//   W1p [68 pairs][132 n]     tf32 slab of W1 (136 k x 128 n)
//   Hp  [64 pairs][68 rows]   tf32 H chunk (128 cols)
//   W2p [16 pairs][260 n]     tf32 32-k sub-slice of W2
//   b1s[512] b2s[256] hs[64]  => 217,216 B total

#define NSTEPS  20
#define THREADS 256
#define LATENT  256
#define UDIM    16
#define HIDDEN  512

#define ZS_OFF  0
#define ZS_SZ   (136*68)
#define W1P_OFF (ZS_OFF + ZS_SZ)
#define W1P_SZ  (68*132)
#define HP_OFF  (W1P_OFF + W1P_SZ)
#define HP_SZ   (64*68)
#define W2P_OFF (HP_OFF + HP_SZ)
#define W2P_SZ  (16*260)
#define SMEM8   (W2P_OFF + W2P_SZ)
#define SMEM_BYTES (SMEM8*8 + (512+256+64)*4)

__device__ __forceinline__ uint32_t f2tf(float f) {
    uint32_t u; asm("cvt.rna.tf32.f32 %0, %1;" : "=r"(u) : "f"(f)); return u;
}
__device__ __forceinline__ float tanh_hw(float x) {
    float y; asm("tanh.approx.f32 %0, %1;" : "=f"(y) : "f"(x)); return y;
}
__device__ __forceinline__ void mma8(float* d, uint32_t a0, uint32_t a1,
                                     uint32_t a2, uint32_t a3,
                                     uint32_t b0, uint32_t b1) {
    asm("mma.sync.aligned.m16n8k8.row.col.f32.tf32.tf32.f32 "
        "{%0,%1,%2,%3}, {%4,%5,%6,%7}, {%8,%9}, {%0,%1,%2,%3};"
        : "+f"(d[0]), "+f"(d[1]), "+f"(d[2]), "+f"(d[3])
        : "r"(a0), "r"(a1), "r"(a2), "r"(a3), "r"(b0), "r"(b1));
}

// ---- staging helpers: fully unrolled register batches (high MLP) ----
__device__ __forceinline__ void w1_load(const float* __restrict__ W1, int c4, int slab,
                                        int batch, int tid, float* wA, float* wB) {
    #pragma unroll
    for (int it = 0; it < 17; it++) {
        int idx = tid + THREADS * (batch * 17 + it);
        int n = idx & 127, pl = idx >> 7;
        int klo = slab * 136 + ((pl >> 2) << 3) + (pl & 3);
        const float* p = W1 + (size_t)klo * HIDDEN + c4 * 128 + n;
        wA[it] = p[0];
        wB[it] = p[4 * HIDDEN];
    }
}
__device__ __forceinline__ void w1_store(uint2* W1p, int batch, int tid,
                                         const float* wA, const float* wB) {
    #pragma unroll
    for (int it = 0; it < 17; it++) {
        int idx = tid + THREADS * (batch * 17 + it);
        int n = idx & 127, pl = idx >> 7;
        W1p[pl * 132 + n] = make_uint2(f2tf(wA[it]), f2tf(wB[it]));
    }
}
__device__ __forceinline__ void w2_load(const float* __restrict__ W2, int c4, int sub,
                                        int tid, float* wC, float* wD) {
    #pragma unroll
    for (int it = 0; it < 16; it++) {
        int idx = tid + THREADS * it;
        int n = idx & 255, pl = idx >> 8;
        int klo = c4 * 128 + sub * 32 + ((pl >> 2) << 3) + (pl & 3);
        const float* p = W2 + (size_t)klo * LATENT + n;
        wC[it] = p[0];
        wD[it] = p[4 * LATENT];
    }
}
__device__ __forceinline__ void w2_store(uint2* W2p, int tid,
                                         const float* wC, const float* wD) {
    #pragma unroll
    for (int it = 0; it < 16; it++) {
        int idx = tid + THREADS * it;
        int n = idx & 255, pl = idx >> 8;
        W2p[pl * 260 + n] = make_uint2(f2tf(wC[it]), f2tf(wD[it]));
    }
}

__global__ __launch_bounds__(THREADS, 1)
void node_euler_hmma3(const float* __restrict__ zt,
                      const float* __restrict__ dt,
                      const float* __restrict__ ut,
                      const float* __restrict__ W1,
                      const float* __restrict__ b1,
                      const float* __restrict__ W2,
                      const float* __restrict__ b2,
                      float* __restrict__ out)
{
    extern __shared__ uint2 sm8[];
    float2* Zs  = (float2*)(sm8 + ZS_OFF);
    uint2*  W1p = sm8 + W1P_OFF;
    uint2*  Hp  = sm8 + HP_OFF;
    uint2*  W2p = sm8 + W2P_OFF;
    float*  b1s = (float*)(sm8 + SMEM8);
    float*  b2s = b1s + 512;
    float*  hs  = b2s + 256;

    const int tid  = threadIdx.x;
    const int w    = tid >> 5, lane = tid & 31;
    const int g    = lane >> 2, tig = lane & 3;
    const int wm   = w >> 2;          // 0..1
    const int wn   = w & 3;           // 0..3
    const int m0   = wm * 32;
    const int row0 = blockIdx.x * 64;

    // ---- init ----
    for (int i = tid; i < HIDDEN; i += THREADS) b1s[i] = b1[i];
    b2s[tid] = b2[tid];
    if (tid < 64) hs[tid] = dt[row0 + tid] * (1.0f / NSTEPS);
    for (int i = tid; i < 136 * 64; i += THREADS) {
        int pp = i >> 6, r = i & 63;
        int klo = ((pp >> 2) << 3) + (pp & 3);
        float lo, hi;
        if (pp < 128) {
            const float* z = zt + (size_t)(row0 + r) * LATENT;
            lo = z[klo]; hi = z[klo + 4];
        } else {
            const float* u = ut + (size_t)(row0 + r) * UDIM;
            lo = u[klo - 256]; hi = u[klo - 252];
        }
        Zs[pp * 68 + r] = make_float2(lo, hi);
    }
    __syncthreads();

    float hr[2][2];
    #pragma unroll
    for (int mt = 0; mt < 2; mt++) {
        hr[mt][0] = hs[m0 + mt * 16 + g];
        hr[mt][1] = hs[m0 + mt * 16 + g + 8];
    }

    float d2[2][8][4];
    #pragma unroll
    for (int mt = 0; mt < 2; mt++)
        #pragma unroll
        for (int nt = 0; nt < 8; nt++)
            d2[mt][nt][0] = d2[mt][nt][1] = d2[mt][nt][2] = d2[mt][nt][3] = 0.0f;

#define MMA_SLAB(slab_) do {                                                   \
    _Pragma("unroll 1")                                                        \
    for (int ktl = 0; ktl < 17; ktl++) {                                       \
        int p_ = ((slab_) * 17 + ktl) * 4 + tig;                               \
        float2 A00 = Zs[p_ * 68 + m0 + g];                                     \
        float2 A01 = Zs[p_ * 68 + m0 + g + 8];                                 \
        float2 A10 = Zs[p_ * 68 + m0 + 16 + g];                                \
        float2 A11 = Zs[p_ * 68 + m0 + 16 + g + 8];                            \
        uint32_t x00 = f2tf(A00.x), x01 = f2tf(A01.x);                         \
        uint32_t y00 = f2tf(A00.y), y01 = f2tf(A01.y);                         \
        uint32_t x10 = f2tf(A10.x), x11 = f2tf(A11.x);                         \
        uint32_t y10 = f2tf(A10.y), y11 = f2tf(A11.y);                         \
        int pl_ = ktl * 4 + tig;                                               \
        _Pragma("unroll")                                                      \
        for (int tn = 0; tn < 4; tn++) {                                       \
            uint2 B = W1p[pl_ * 132 + wn * 32 + tn * 8 + g];                   \
            mma8(d1[0][tn], x00, x01, y00, y01, B.x, B.y);                     \
            mma8(d1[1][tn], x10, x11, y10, y11, B.x, B.y);                     \
        }                                                                      \
    }                                                                          \
} while (0)

#define MMA_SUB(sub_) do {                                                     \
    _Pragma("unroll")                                                          \
    for (int kt2 = 0; kt2 < 4; kt2++) {                                        \
        int ph = ((sub_) * 4 + kt2) * 4 + tig;                                 \
        uint2 A00 = Hp[ph * 68 + m0 + g];                                      \
        uint2 A01 = Hp[ph * 68 + m0 + g + 8];                                  \
        uint2 A10 = Hp[ph * 68 + m0 + 16 + g];                                 \
        uint2 A11 = Hp[ph * 68 + m0 + 16 + g + 8];                             \
        int pl_ = kt2 * 4 + tig;                                               \
        _Pragma("unroll")                                                      \
        for (int nt = 0; nt < 8; nt++) {                                       \
            uint2 B = W2p[pl_ * 260 + wn * 64 + nt * 8 + g];                   \
            mma8(d2[0][nt], A00.x, A01.x, A00.y, A01.y, B.x, B.y);             \
            mma8(d2[1][nt], A10.x, A11.x, A10.y, A11.y, B.x, B.y);             \
        }                                                                      \
    }                                                                          \
} while (0)

    for (int s = 0; s < NSTEPS; s++) {
        #pragma unroll 1
        for (int c4 = 0; c4 < 4; c4++) {
            float d1[2][4][4];
            #pragma unroll
            for (int mt = 0; mt < 2; mt++)
                #pragma unroll
                for (int tn = 0; tn < 4; tn++)
                    d1[mt][tn][0] = d1[mt][tn][1] = d1[mt][tn][2] = d1[mt][tn][3] = 0.0f;

            // ===== GEMM1: slab0 staged, slab1 prefetched under slab0's MMA =====
            {
                float wA[17], wB[17], pA[17], pB[17];
                w1_load(W1, c4, 0, 0, tid, wA, wB);   // batched LDG, MLP 34
                w1_store(W1p, 0, tid, wA, wB);        // W1p free (barriers upstream)
                w1_load(W1, c4, 0, 1, tid, wA, wB);
                w1_store(W1p, 1, tid, wA, wB);
                w1_load(W1, c4, 1, 0, tid, pA, pB);   // prefetch slab1.b0 (no SMEM)
                __syncthreads();                      // slab0 visible
                MMA_SLAB(0);
                __syncthreads();                      // WAR: slab0 readers done
                w1_store(W1p, 0, tid, pA, pB);
                w1_load(W1, c4, 1, 1, tid, wA, wB);
                w1_store(W1p, 1, tid, wA, wB);
                __syncthreads();                      // slab1 visible
                MMA_SLAB(1);
            }

            // ===== bias + tanh -> Hp (tf32 pairs) =====
            {
                uint32_t* Hf = (uint32_t*)Hp;
                #pragma unroll
                for (int mt = 0; mt < 2; mt++)
                    #pragma unroll
                    for (int tn = 0; tn < 4; tn++) {
                        int lc = wn * 32 + tn * 8 + 2 * tig;
                        int gc = c4 * 128 + lc;
                        float bv0 = b1s[gc], bv1 = b1s[gc + 1];
                        int r  = m0 + mt * 16 + g;
                        int p0 = ((lc >> 3) << 2) + (lc & 3), h0 = (lc >> 2) & 1;
                        int l1 = lc + 1;
                        int p1 = ((l1 >> 3) << 2) + (l1 & 3), h1 = (l1 >> 2) & 1;
                        Hf[(p0 * 68 + r) * 2 + h0]     = f2tf(tanh_hw(d1[mt][tn][0] + bv0));
                        Hf[(p1 * 68 + r) * 2 + h1]     = f2tf(tanh_hw(d1[mt][tn][1] + bv1));
                        Hf[(p0 * 68 + r + 8) * 2 + h0] = f2tf(tanh_hw(d1[mt][tn][2] + bv0));
                        Hf[(p1 * 68 + r + 8) * 2 + h1] = f2tf(tanh_hw(d1[mt][tn][3] + bv1));
                    }
            }

            // ===== GEMM2: 4 k-subs, each sub's LDGs prefetched under prior MMA =====
            {
                float wC[16], wD[16];
                w2_load(W2, c4, 0, tid, wC, wD);      // prefetch sub0
                __syncthreads();                      // Hp visible (+ W2p WAR covered)
                w2_store(W2p, tid, wC, wD);
                w2_load(W2, c4, 1, tid, wC, wD);      // prefetch sub1
                __syncthreads();
                MMA_SUB(0);
                __syncthreads();
                w2_store(W2p, tid, wC, wD);
                w2_load(W2, c4, 2, tid, wC, wD);
                __syncthreads();
                MMA_SUB(1);
                __syncthreads();
                w2_store(W2p, tid, wC, wD);
                w2_load(W2, c4, 3, tid, wC, wD);
                __syncthreads();
                MMA_SUB(2);
                __syncthreads();
                w2_store(W2p, tid, wC, wD);
                __syncthreads();
                MMA_SUB(3);
            }
        }

        // ---- z += h * (d2 + b2) in-place (fp32 SMEM, single-owner); reset d2 ----
        {
            float* Zf = (float*)Zs;
            #pragma unroll
            for (int mt = 0; mt < 2; mt++)
                #pragma unroll
                for (int nt = 0; nt < 8; nt++) {
                    int c = wn * 64 + nt * 8 + 2 * tig;
                    int r = m0 + mt * 16 + g;
                    int p0 = ((c >> 3) << 2) + (c & 3), h0 = (c >> 2) & 1;
                    int c1 = c + 1;
                    int p1 = ((c1 >> 3) << 2) + (c1 & 3), h1 = (c1 >> 2) & 1;
                    Zf[(p0 * 68 + r) * 2 + h0]       += hr[mt][0] * (d2[mt][nt][0] + b2s[c]);
                    Zf[(p1 * 68 + r) * 2 + h1]       += hr[mt][0] * (d2[mt][nt][1] + b2s[c + 1]);
                    Zf[(p0 * 68 + r + 8) * 2 + h0]   += hr[mt][1] * (d2[mt][nt][2] + b2s[c]);
                    Zf[(p1 * 68 + r + 8) * 2 + h1]   += hr[mt][1] * (d2[mt][nt][3] + b2s[c + 1]);
                    d2[mt][nt][0] = d2[mt][nt][1] = d2[mt][nt][2] = d2[mt][nt][3] = 0.0f;
                }
        }
        __syncthreads();   // Zs updated before next step's GEMM1 reads
    }

    // ---- write result (coalesced over k) ----
    {
        const float* Zf = (const float*)Zs;
        for (int i = tid; i < 64 * LATENT; i += THREADS) {
            int r = i >> 8, k = i & 255;
            int p = ((k >> 3) << 2) + (k & 3), h = (k >> 2) & 1;
            out[(size_t)(row0 + r) * LATENT + k] = Zf[(p * 68 + r) * 2 + h];
        }
    }
}

extern "C" void kernel_launch(void* const* d_in, const int* in_sizes, int n_in,
                              void* d_out, int out_size)
{
    const float* zt = (const float*)d_in[0];
    const float* dt = (const float*)d_in[1];
    const float* ut = (const float*)d_in[2];
    const float* W1 = (const float*)d_in[3];
    const float* b1 = (const float*)d_in[4];
    const float* W2 = (const float*)d_in[5];
    const float* b2 = (const float*)d_in[6];
    float* out = (float*)d_out;

    cudaFuncSetAttribute(node_euler_hmma3,
                         cudaFuncAttributeMaxDynamicSharedMemorySize, SMEM_BYTES);

    node_euler_hmma3<<<128, THREADS, SMEM_BYTES>>>(zt, dt, ut, W1, b1, W2, b2, out);
}